// round 4
// baseline (speedup 1.0000x reference)
#include <cuda_runtime.h>
#include <cstdint>

// B=16, T=512, E=256, H=256, HEADS=8, NL=3, NC=10

// ---------------- scratch (static device memory) -----------------------------
__device__ __align__(16) float g_M[16*512*512];
__device__ __align__(16) float g_cat[8192*512];
__device__ __align__(16) float g_c1[8192*256];
__device__ __align__(16) float g_next[8192*256];
__device__ __align__(16) float g_xg[8192*768];
__device__ __align__(16) float g_out[8192*256];
__device__ __align__(16) float g_u[8192*256];
__device__ __align__(16) float g_a[8192*8];
__device__ __align__(16) float g_sent[16*256];

// ---------------- helpers ----------------------------------------------------
__device__ __forceinline__ uint32_t smem_u32(const void* p) {
    uint32_t a;
    asm("{ .reg .u64 t; cvta.to.shared.u64 t, %1; cvt.u32.u64 %0, t; }"
        : "=r"(a) : "l"(p));
    return a;
}
__device__ __forceinline__ uint32_t mapa_rank(uint32_t laddr, int rank) {
    uint32_t r;
    asm("mapa.shared::cluster.u32 %0, %1, %2;" : "=r"(r) : "r"(laddr), "r"(rank));
    return r;
}
__device__ __forceinline__ void st_cluster(uint32_t raddr, float v) {
    asm volatile("st.shared::cluster.f32 [%0], %1;" :: "r"(raddr), "f"(v) : "memory");
}

// ---------------- 1. embedding gather ----------------------------------------
__global__ void embed_kernel(const int* __restrict__ x, const float* __restrict__ emb) {
    int m = blockIdx.x;
    int tok = x[m];
    float4 v = *(const float4*)(emb + (size_t)tok * 256 + threadIdx.x * 4);
    *(float4*)(g_cat + (size_t)m * 512 + threadIdx.x * 4) = v;
}

// ---------------- 2. M = sum_l w_l*G + (1-w_l)*G_prod ------------------------
__global__ void mix_kernel(const float* __restrict__ G, const float* __restrict__ Gp,
                           const float* __restrict__ mw) {
    int i = blockIdx.x * blockDim.x + threadIdx.x;
    float w0 = mw[0], w1 = mw[1], w2 = mw[2];
    int b = i >> 16;
    int r = i & 65535;
    const float4* G4  = (const float4*)G;
    const float4* Gp4 = (const float4*)Gp;
    size_t base = (size_t)b * 3 * 65536 + r;
    float4 g0 = G4[base],           p0 = Gp4[base];
    float4 g1 = G4[base + 65536],   p1 = Gp4[base + 65536];
    float4 g2 = G4[base + 131072],  p2 = Gp4[base + 131072];
    float4 o;
    o.x = w0*g0.x + (1.f-w0)*p0.x + w1*g1.x + (1.f-w1)*p1.x + w2*g2.x + (1.f-w2)*p2.x;
    o.y = w0*g0.y + (1.f-w0)*p0.y + w1*g1.y + (1.f-w1)*p1.y + w2*g2.y + (1.f-w2)*p2.y;
    o.z = w0*g0.z + (1.f-w0)*p0.z + w1*g1.z + (1.f-w1)*p1.z + w2*g2.z + (1.f-w2)*p2.z;
    o.w = w0*g0.w + (1.f-w0)*p0.w + w1*g1.w + (1.f-w1)*p1.w + w2*g2.w + (1.f-w2)*p2.w;
    ((float4*)g_M)[i] = o;
}

// ---------------- 128x128 GEMM, 8x8 microtile --------------------------------
// TA=1: A is K x M (k-major). TA=0: A is M x K row-major.
// TB=1: B is N x K row-major. TB=0: B is K x N.
// MODE: 0 plain, 1 +bias, 2 tanh(+bias), 3 GLU: C = aux * sigmoid(acc)
template<int TA, int TB, int MODE>
__global__ void __launch_bounds__(256) gemm128(
    const float* __restrict__ A, int lda,
    const float* __restrict__ B, int ldb,
    float* __restrict__ C, int ldc, int K,
    const float* __restrict__ bias, const float* __restrict__ aux,
    size_t sA, size_t sB, size_t sC)
{
    A += sA * blockIdx.z; B += sB * blockIdx.z; C += sC * blockIdx.z;
    if (MODE == 3) aux += sC * blockIdx.z;
    __shared__ __align__(16) float As[16][132];
    __shared__ __align__(16) float Bs[16][132];
    int tid = threadIdx.x;
    int m0 = blockIdx.x * 128, n0 = blockIdx.y * 128;
    int tm = (tid >> 4) * 8, tn = (tid & 15) * 8;

    float acc[8][8];
#pragma unroll
    for (int i = 0; i < 8; ++i)
#pragma unroll
        for (int j = 0; j < 8; ++j) acc[i][j] = 0.f;

    for (int k0 = 0; k0 < K; k0 += 16) {
        float4 a0, a1, b0, b1;
        if (TA == 0) {
            const float* s = A + (size_t)(m0 + (tid >> 1)) * lda + k0 + (tid & 1) * 8;
            a0 = *(const float4*)s; a1 = *(const float4*)(s + 4);
        } else {
            const float* s = A + (size_t)(k0 + (tid >> 4)) * lda + m0 + (tid & 15) * 8;
            a0 = *(const float4*)s; a1 = *(const float4*)(s + 4);
        }
        if (TB == 1) {
            const float* s = B + (size_t)(n0 + (tid >> 1)) * ldb + k0 + (tid & 1) * 8;
            b0 = *(const float4*)s; b1 = *(const float4*)(s + 4);
        } else {
            const float* s = B + (size_t)(k0 + (tid >> 4)) * ldb + n0 + (tid & 15) * 8;
            b0 = *(const float4*)s; b1 = *(const float4*)(s + 4);
        }
        __syncthreads();
        if (TA == 0) {
            int r = tid >> 1, kc = (tid & 1) * 8;
            As[kc+0][r] = a0.x; As[kc+1][r] = a0.y; As[kc+2][r] = a0.z; As[kc+3][r] = a0.w;
            As[kc+4][r] = a1.x; As[kc+5][r] = a1.y; As[kc+6][r] = a1.z; As[kc+7][r] = a1.w;
        } else {
            int kk = tid >> 4, mc = (tid & 15) * 8;
            *(float4*)&As[kk][mc]     = a0;
            *(float4*)&As[kk][mc + 4] = a1;
        }
        if (TB == 1) {
            int r = tid >> 1, kc = (tid & 1) * 8;
            Bs[kc+0][r] = b0.x; Bs[kc+1][r] = b0.y; Bs[kc+2][r] = b0.z; Bs[kc+3][r] = b0.w;
            Bs[kc+4][r] = b1.x; Bs[kc+5][r] = b1.y; Bs[kc+6][r] = b1.z; Bs[kc+7][r] = b1.w;
        } else {
            int kk = tid >> 4, nc = (tid & 15) * 8;
            *(float4*)&Bs[kk][nc]     = b0;
            *(float4*)&Bs[kk][nc + 4] = b1;
        }
        __syncthreads();
#pragma unroll
        for (int kk = 0; kk < 16; ++kk) {
            float a8[8], b8[8];
            *(float4*)&a8[0] = *(const float4*)&As[kk][tm];
            *(float4*)&a8[4] = *(const float4*)&As[kk][tm + 4];
            *(float4*)&b8[0] = *(const float4*)&Bs[kk][tn];
            *(float4*)&b8[4] = *(const float4*)&Bs[kk][tn + 4];
#pragma unroll
            for (int i = 0; i < 8; ++i)
#pragma unroll
                for (int j = 0; j < 8; ++j)
                    acc[i][j] = fmaf(a8[i], b8[j], acc[i][j]);
        }
    }
    // epilogue
    float bias8[8];
#pragma unroll
    for (int j = 0; j < 8; ++j) bias8[j] = (MODE == 1 || MODE == 2) ? bias[n0 + tn + j] : 0.f;
#pragma unroll
    for (int i = 0; i < 8; ++i) {
        size_t row = (size_t)(m0 + tm + i) * ldc + n0 + tn;
        float vv[8];
#pragma unroll
        for (int j = 0; j < 8; ++j) {
            float t = acc[i][j];
            if (MODE == 1) t += bias8[j];
            if (MODE == 2) t = tanhf(t + bias8[j]);
            vv[j] = t;
        }
        if (MODE == 3) {
            float4 av0 = *(const float4*)(aux + row);
            float4 av1 = *(const float4*)(aux + row + 4);
            float a8v[8] = {av0.x, av0.y, av0.z, av0.w, av1.x, av1.y, av1.z, av1.w};
#pragma unroll
            for (int j = 0; j < 8; ++j) vv[j] = a8v[j] / (1.f + __expf(-vv[j]));
        }
        float4 o0 = {vv[0], vv[1], vv[2], vv[3]};
        float4 o1 = {vv[4], vv[5], vv[6], vv[7]};
        *(float4*)(C + row)     = o0;
        *(float4*)(C + row + 4) = o1;
    }
}

// ---------------- GRU scan: 16 clusters x 8 CTAs, mbarrier sync --------------
__global__ void __launch_bounds__(256, 1) __cluster_dims__(8, 1, 1)
scan_kernel(const float* __restrict__ xg, const float* __restrict__ Whh,
            const float* __restrict__ bhh, const float* __restrict__ h0)
{
    __shared__ __align__(16) float h[2][256];
    __shared__ __align__(8) unsigned long long mbar[2];
    int tid  = threadIdx.x;
    int rank = blockIdx.x & 7;
    int b    = blockIdx.x >> 3;
    int pair = tid >> 3;          // 0..31
    int sub  = tid & 7;
    int j    = rank * 32 + pair;  // 0..255

    float4 w[3][8];
#pragma unroll
    for (int g = 0; g < 3; ++g) {
        const float* row = Whh + (size_t)(g * 256 + j) * 256;
#pragma unroll
        for (int i = 0; i < 8; ++i)
            w[g][i] = *(const float4*)(row + i * 32 + sub * 4);
    }
    float b_r = 0.f, b_z = 0.f, b_n = 0.f;
    if (sub == 0) { b_r = bhh[j]; b_z = bhh[256 + j]; b_n = bhh[512 + j]; }

    if (tid == 0) {
        uint32_t m0a = smem_u32(&mbar[0]);
        asm volatile("mbarrier.init.shared.b64 [%0], 8;" :: "r"(m0a) : "memory");
        asm volatile("mbarrier.init.shared.b64 [%0], 8;" :: "r"(m0a + 8) : "memory");
    }
    h[0][tid] = h0[b * 256 + tid];
    uint32_t hbase[2] = { smem_u32(&h[0][0]), smem_u32(&h[1][0]) };
    uint32_t barloc[2] = { smem_u32(&mbar[0]), smem_u32(&mbar[1]) };
    // remote h addresses (per owner lane, both buffers, all 8 ranks)
    uint32_t raddr[2][8];
    if (sub == 0) {
#pragma unroll
        for (int rk = 0; rk < 8; ++rk) {
            raddr[0][rk] = mapa_rank(hbase[0] + (uint32_t)j * 4u, rk);
            raddr[1][rk] = mapa_rank(hbase[1] + (uint32_t)j * 4u, rk);
        }
    }
    uint32_t rbar = 0;
    if (tid < 8) rbar = mapa_rank(barloc[0], tid);   // bar[1] = rbar+8
    __syncthreads();
    asm volatile("barrier.cluster.arrive.aligned;" ::: "memory");
    asm volatile("barrier.cluster.wait.aligned;"  ::: "memory");

    // xg prefetch for t=0
    float xr = 0.f, xz = 0.f, xn = 0.f;
    if (sub == 0) {
        const float* xrow = xg + (size_t)(b * 512) * 768;
        xr = xrow[j]; xz = xrow[256 + j]; xn = xrow[512 + j];
    }

    int p = 0;
    for (int t = 0; t < 512; ++t) {
        float hold = 0.f;
        if (sub == 0) hold = h[p][j];
        float ar = 0.f, az = 0.f, an = 0.f;
#pragma unroll
        for (int i = 0; i < 8; ++i) {
            float4 hv = *(const float4*)&h[p][i * 32 + sub * 4];
            ar = fmaf(w[0][i].x, hv.x, ar); ar = fmaf(w[0][i].y, hv.y, ar);
            ar = fmaf(w[0][i].z, hv.z, ar); ar = fmaf(w[0][i].w, hv.w, ar);
            az = fmaf(w[1][i].x, hv.x, az); az = fmaf(w[1][i].y, hv.y, az);
            az = fmaf(w[1][i].z, hv.z, az); az = fmaf(w[1][i].w, hv.w, az);
            an = fmaf(w[2][i].x, hv.x, an); an = fmaf(w[2][i].y, hv.y, an);
            an = fmaf(w[2][i].z, hv.z, an); an = fmaf(w[2][i].w, hv.w, an);
        }
#pragma unroll
        for (int off = 4; off; off >>= 1) {
            ar += __shfl_down_sync(0xffffffffu, ar, off, 8);
            az += __shfl_down_sync(0xffffffffu, az, off, 8);
            an += __shfl_down_sync(0xffffffffu, an, off, 8);
        }
        if (sub == 0) {
            float r_ = 1.f / (1.f + __expf(-(xr + ar + b_r)));
            float z_ = 1.f / (1.f + __expf(-(xz + az + b_z)));
            float n_ = tanhf(xn + r_ * (an + b_n));
            float hv = (1.f - z_) * n_ + z_ * hold;
            g_out[(size_t)(b * 512 + t) * 256 + j] = hv;
#pragma unroll
            for (int rk = 0; rk < 8; ++rk) st_cluster(raddr[p ^ 1][rk], hv);
            asm volatile("fence.acq_rel.cluster;" ::: "memory");
        }
        __syncthreads();
        if (tid < 8) {
            uint32_t rb = rbar + (uint32_t)((t & 1) * 8);
            asm volatile("mbarrier.arrive.release.cluster.shared::cluster.b64 _, [%0];"
                         :: "r"(rb) : "memory");
        }
        // prefetch next xg while the barrier drains
        if (sub == 0 && t < 511) {
            const float* xrow = xg + (size_t)(b * 512 + t + 1) * 768;
            xr = xrow[j]; xz = xrow[256 + j]; xn = xrow[512 + j];
        }
        {
            uint32_t bl = barloc[t & 1];
            uint32_t parity = (uint32_t)((t >> 1) & 1);
            asm volatile(
                "{\n\t"
                ".reg .pred P1;\n\t"
                "WL_%=:\n\t"
                "mbarrier.try_wait.parity.acquire.cluster.shared::cta.b64 P1, [%0], %1, 0x989680;\n\t"
                "@P1 bra.uni WD_%=;\n\t"
                "bra.uni WL_%=;\n\t"
                "WD_%=:\n\t"
                "}"
                :: "r"(bl), "r"(parity) : "memory");
        }
        p ^= 1;
    }
}

// ---------------- attention logits: a = u @ W2^T + b2 ------------------------
__global__ void __launch_bounds__(256) logits_kernel(const float* __restrict__ W2,
                                                     const float* __restrict__ b2) {
    __shared__ float sW[8 * 256];
    for (int i = threadIdx.x; i < 2048; i += 256) sW[i] = W2[i];
    __syncthreads();
    int warp = threadIdx.x >> 5, lane = threadIdx.x & 31;
    int m = blockIdx.x * 8 + warp;
    const float* ur = g_u + (size_t)m * 256;
    float uv[8];
#pragma unroll
    for (int i = 0; i < 8; ++i) uv[i] = ur[i * 32 + lane];
#pragma unroll
    for (int hh = 0; hh < 8; ++hh) {
        float acc = 0.f;
#pragma unroll
        for (int i = 0; i < 8; ++i) acc = fmaf(uv[i], sW[hh * 256 + i * 32 + lane], acc);
#pragma unroll
        for (int off = 16; off; off >>= 1) acc += __shfl_down_sync(0xffffffffu, acc, off);
        if (lane == 0) g_a[(size_t)m * 8 + hh] = acc + b2[hh];
    }
}

// ---------------- masked softmax over T --------------------------------------
__global__ void softmax_kernel(const int* __restrict__ lengths, float* __restrict__ att) {
    int bh = blockIdx.x, b = bh >> 3, hh = bh & 7;
    int t = threadIdx.x;
    int len = lengths[b];
    float v = (t < len) ? g_a[(size_t)(b * 512 + t) * 8 + hh] : -1e30f;
    __shared__ float red[16];
    __shared__ float bc[2];
    float m = v;
#pragma unroll
    for (int o = 16; o; o >>= 1) m = fmaxf(m, __shfl_xor_sync(0xffffffffu, m, o));
    if ((t & 31) == 0) red[t >> 5] = m;
    __syncthreads();
    if (t == 0) {
        float mm = red[0];
        for (int i = 1; i < 16; ++i) mm = fmaxf(mm, red[i]);
        bc[0] = mm;
    }
    __syncthreads();
    float e = __expf(v - bc[0]);
    float s = e;
#pragma unroll
    for (int o = 16; o; o >>= 1) s += __shfl_xor_sync(0xffffffffu, s, o);
    __syncthreads();
    if ((t & 31) == 0) red[t >> 5] = s;
    __syncthreads();
    if (t == 0) {
        float ss = 0.f;
        for (int i = 0; i < 16; ++i) ss += red[i];
        bc[1] = ss;
    }
    __syncthreads();
    att[(size_t)bh * 512 + t] = e / bc[1];
}

// ---------------- sent + avg (+hn copy) --------------------------------------
__global__ void __launch_bounds__(256) sent_kernel(const float* __restrict__ att,
                                                   float* __restrict__ out_hn) {
    int b = blockIdx.x, q = blockIdx.y;
    __shared__ float sat[8][512];
    __shared__ float sred[4][8][64];
    int tid = threadIdx.x;
    for (int i = tid; i < 4096; i += 256) sat[i >> 9][i & 511] = att[(size_t)b * 4096 + i];
    __syncthreads();
    int dl = tid & 63, tc = tid >> 6;
    int d = q * 64 + dl;
    const float* orow = g_out + (size_t)b * 512 * 256;
    float acc[8] = {0.f,0.f,0.f,0.f,0.f,0.f,0.f,0.f};
    for (int t = tc * 128; t < tc * 128 + 128; ++t) {
        float ov = orow[(size_t)t * 256 + d];
#pragma unroll
        for (int hh = 0; hh < 8; ++hh) acc[hh] = fmaf(sat[hh][t], ov, acc[hh]);
    }
#pragma unroll
    for (int hh = 0; hh < 8; ++hh) sred[tc][hh][dl] = acc[hh];
    __syncthreads();
    if (tc == 0) {
        float s = 0.f;
#pragma unroll
        for (int hh = 0; hh < 8; ++hh)
            s += sred[0][hh][dl] + sred[1][hh][dl] + sred[2][hh][dl] + sred[3][hh][dl];
        g_sent[b * 256 + d] = s * 0.125f;
        out_hn[b * 256 + d] = orow[(size_t)511 * 256 + d];
    }
}

// ---------------- final FC ---------------------------------------------------
__global__ void fc_kernel(const float* __restrict__ Wf, const float* __restrict__ bf,
                          float* __restrict__ out_main) {
    int b = blockIdx.x;
    __shared__ float sv[256];
    sv[threadIdx.x] = g_sent[b * 256 + threadIdx.x];
    __syncthreads();
    if (threadIdx.x < 10) {
        float s = bf[threadIdx.x];
        for (int k = 0; k < 256; ++k) s = fmaf(Wf[threadIdx.x * 256 + k], sv[k], s);
        out_main[b * 10 + threadIdx.x] = s;
    }
}

// ============================================================================
extern "C" void kernel_launch(void* const* d_in, const int* in_sizes, int n_in,
                              void* d_out, int out_size) {
    const int*   x    = (const int*)  d_in[0];
    const int*   len  = (const int*)  d_in[1];
    const float* h0   = (const float*)d_in[2];
    const float* emb  = (const float*)d_in[3];
    const float* G    = (const float*)d_in[4];
    const float* Gp   = (const float*)d_in[5];
    const float* mw   = (const float*)d_in[6];
    const float* Wc1  = (const float*)d_in[7];
    const float* Wc2  = (const float*)d_in[8];
    const float* W_ih = (const float*)d_in[9];
    const float* W_hh = (const float*)d_in[10];
    const float* b_ih = (const float*)d_in[11];
    const float* b_hh = (const float*)d_in[12];
    const float* W1   = (const float*)d_in[13];
    const float* b1   = (const float*)d_in[14];
    const float* W2   = (const float*)d_in[15];
    const float* b2   = (const float*)d_in[16];
    const float* Wf   = (const float*)d_in[17];
    const float* bf   = (const float*)d_in[18];

    float* out      = (float*)d_out;
    float* out_main = out;
    float* out_hn   = out + 160;
    float* out_att  = out + 160 + 4096;

    void* p;
    cudaGetSymbolAddress(&p, g_M);    float* pM    = (float*)p;
    cudaGetSymbolAddress(&p, g_cat);  float* pcat  = (float*)p;
    cudaGetSymbolAddress(&p, g_c1);   float* pc1   = (float*)p;
    cudaGetSymbolAddress(&p, g_next); float* pnext = (float*)p;
    cudaGetSymbolAddress(&p, g_xg);   float* pxg   = (float*)p;
    cudaGetSymbolAddress(&p, g_out);  float* pout  = (float*)p;
    cudaGetSymbolAddress(&p, g_u);    float* pu    = (float*)p;

    // 1. embedding gather
    embed_kernel<<<8192, 64>>>(x, emb);
    // 2. adjacency mix
    mix_kernel<<<4096, 256>>>(G, Gp, mw);
    // 3. weighted = M^T @ Hemb -> cat right half
    gemm128<1, 0, 0><<<dim3(4, 2, 16), 256>>>(
        pM, 512, pcat, 512, pcat + 256, 512, 512, nullptr, nullptr,
        (size_t)512 * 512, (size_t)512 * 512, (size_t)512 * 512);
    // 4. c1 = cat @ Wc1^T
    gemm128<0, 1, 0><<<dim3(64, 2), 256>>>(
        pcat, 512, Wc1, 512, pc1, 256, 512, nullptr, nullptr, 0, 0, 0);
    // 5. next = c1 * sigmoid(cat @ Wc2^T)
    gemm128<0, 1, 3><<<dim3(64, 2), 256>>>(
        pcat, 512, Wc2, 512, pnext, 256, 512, nullptr, pc1, 0, 0, 0);
    // 6. xg = next @ W_ih^T + b_ih
    gemm128<0, 1, 1><<<dim3(64, 6), 256>>>(
        pnext, 256, W_ih, 256, pxg, 768, 256, b_ih, nullptr, 0, 0, 0);
    // 7. GRU scan
    scan_kernel<<<128, 256>>>(pxg, W_hh, b_hh, h0);
    // 8. u = tanh(out @ W1^T + b1)
    gemm128<0, 1, 2><<<dim3(64, 2), 256>>>(
        pout, 256, W1, 256, pu, 256, 256, b1, nullptr, 0, 0, 0);
    // 9. logits
    logits_kernel<<<1024, 256>>>(W2, b2);
    // 10. masked softmax
    softmax_kernel<<<128, 512>>>(len, out_att);
    // 11. sent + avg + hn
    sent_kernel<<<dim3(16, 4), 256>>>(out_att, out_hn);
    // 12. final FC
    fc_kernel<<<16, 256>>>(Wf, bf, out_main);
}

// round 5
// speedup vs baseline: 1.4944x; 1.4944x over previous
#include <cuda_runtime.h>
#include <cstdint>

// B=16, T=512, E=256, H=256, HEADS=8, NL=3, NC=10

// ---------------- scratch (static device memory) -----------------------------
__device__ __align__(16) float g_M[16*512*512];
__device__ __align__(16) float g_cat[8192*512];
__device__ __align__(16) float g_c1[8192*256];
__device__ __align__(16) float g_next[8192*256];
__device__ __align__(16) float g_xg[8192*768];
__device__ __align__(16) float g_out[8192*256];
__device__ __align__(16) float g_u[8192*256];
__device__ __align__(16) float g_a[8192*8];
__device__ __align__(16) float g_sent[16*256];

// ---------------- helpers ----------------------------------------------------
__device__ __forceinline__ uint32_t smem_u32(const void* p) {
    uint32_t a;
    asm("{ .reg .u64 t; cvta.to.shared.u64 t, %1; cvt.u32.u64 %0, t; }"
        : "=r"(a) : "l"(p));
    return a;
}
__device__ __forceinline__ uint32_t mapa_rank(uint32_t laddr, int rank) {
    uint32_t r;
    asm("mapa.shared::cluster.u32 %0, %1, %2;" : "=r"(r) : "r"(laddr), "r"(rank));
    return r;
}
// remote store that deposits its completion (4 bytes) into the remote mbarrier
__device__ __forceinline__ void st_async_f32(uint32_t raddr, float v, uint32_t rmbar) {
    asm volatile(
        "st.async.weak.shared::cluster.mbarrier::complete_tx::bytes.b32 [%0], %1, [%2];"
        :: "r"(raddr), "r"(__float_as_uint(v)), "r"(rmbar) : "memory");
}

// ---------------- 1. embedding gather ----------------------------------------
__global__ void embed_kernel(const int* __restrict__ x, const float* __restrict__ emb) {
    int m = blockIdx.x;
    int tok = x[m];
    float4 v = *(const float4*)(emb + (size_t)tok * 256 + threadIdx.x * 4);
    *(float4*)(g_cat + (size_t)m * 512 + threadIdx.x * 4) = v;
}

// ---------------- 2. M = sum_l w_l*G + (1-w_l)*G_prod ------------------------
__global__ void mix_kernel(const float* __restrict__ G, const float* __restrict__ Gp,
                           const float* __restrict__ mw) {
    int i = blockIdx.x * blockDim.x + threadIdx.x;
    float w0 = mw[0], w1 = mw[1], w2 = mw[2];
    int b = i >> 16;
    int r = i & 65535;
    const float4* G4  = (const float4*)G;
    const float4* Gp4 = (const float4*)Gp;
    size_t base = (size_t)b * 3 * 65536 + r;
    float4 g0 = G4[base],           p0 = Gp4[base];
    float4 g1 = G4[base + 65536],   p1 = Gp4[base + 65536];
    float4 g2 = G4[base + 131072],  p2 = Gp4[base + 131072];
    float4 o;
    o.x = w0*g0.x + (1.f-w0)*p0.x + w1*g1.x + (1.f-w1)*p1.x + w2*g2.x + (1.f-w2)*p2.x;
    o.y = w0*g0.y + (1.f-w0)*p0.y + w1*g1.y + (1.f-w1)*p1.y + w2*g2.y + (1.f-w2)*p2.y;
    o.z = w0*g0.z + (1.f-w0)*p0.z + w1*g1.z + (1.f-w1)*p1.z + w2*g2.z + (1.f-w2)*p2.z;
    o.w = w0*g0.w + (1.f-w0)*p0.w + w1*g1.w + (1.f-w1)*p1.w + w2*g2.w + (1.f-w2)*p2.w;
    ((float4*)g_M)[i] = o;
}

// ---------------- generic 128x64 GEMM (Round-3 proven config) ----------------
// TRANSA=1: A is K x M (k-major).  TRANSA=0: A is M x K row-major.
// TRANSB=1: B is N x K row-major.  TRANSB=0: B is K x N.
// MODE: 0 plain, 1 +bias, 2 tanh(+bias), 3 GLU: C = aux * sigmoid(acc)
template<int TRANSA, int TRANSB, int MODE>
__global__ void __launch_bounds__(256) gemm128(
    const float* __restrict__ A, int lda,
    const float* __restrict__ B, int ldb,
    float* __restrict__ C, int ldc, int K,
    const float* __restrict__ bias, const float* __restrict__ aux,
    size_t sA, size_t sB, size_t sC)
{
    A += sA * blockIdx.z; B += sB * blockIdx.z; C += sC * blockIdx.z;
    if (MODE == 3) aux += sC * blockIdx.z;
    __shared__ __align__(16) float As[16][132];
    __shared__ __align__(16) float Bs[16][68];
    int tid = threadIdx.x;
    int m0b = blockIdx.x * 128, n0b = blockIdx.y * 64;
    int tm = tid >> 4, tn = tid & 15;

    float acc[8][4];
#pragma unroll
    for (int i = 0; i < 8; ++i)
#pragma unroll
        for (int j = 0; j < 4; ++j) acc[i][j] = 0.f;

    for (int k0 = 0; k0 < K; k0 += 16) {
        float4 a0, a1, b0;
        int akk = 0, amc = 0, ar = 0, akc = 0;
        if (TRANSA) {
            akk = tid >> 4; amc = (tid & 15) * 8;
            const float* src = A + (size_t)(k0 + akk) * lda + m0b + amc;
            a0 = *(const float4*)src;
            a1 = *(const float4*)(src + 4);
        } else {
            ar = tid >> 1; akc = (tid & 1) * 8;
            const float* src = A + (size_t)(m0b + ar) * lda + k0 + akc;
            a0 = *(const float4*)src;
            a1 = *(const float4*)(src + 4);
        }
        int bn = 0, bkc = 0, bkk = 0, bnc = 0;
        if (TRANSB) {
            bn = tid >> 2; bkc = (tid & 3) * 4;
            b0 = *(const float4*)(B + (size_t)(n0b + bn) * ldb + k0 + bkc);
        } else {
            bkk = tid >> 4; bnc = (tid & 15) * 4;
            b0 = *(const float4*)(B + (size_t)(k0 + bkk) * ldb + n0b + bnc);
        }
        __syncthreads();
        if (TRANSA) {
            *(float4*)&As[akk][amc]     = a0;
            *(float4*)&As[akk][amc + 4] = a1;
        } else {
            As[akc+0][ar] = a0.x; As[akc+1][ar] = a0.y;
            As[akc+2][ar] = a0.z; As[akc+3][ar] = a0.w;
            As[akc+4][ar] = a1.x; As[akc+5][ar] = a1.y;
            As[akc+6][ar] = a1.z; As[akc+7][ar] = a1.w;
        }
        if (TRANSB) {
            Bs[bkc+0][bn] = b0.x; Bs[bkc+1][bn] = b0.y;
            Bs[bkc+2][bn] = b0.z; Bs[bkc+3][bn] = b0.w;
        } else {
            *(float4*)&Bs[bkk][bnc] = b0;
        }
        __syncthreads();
#pragma unroll
        for (int kk = 0; kk < 16; ++kk) {
            float a8[8], b4[4];
            *(float4*)&a8[0] = *(const float4*)&As[kk][tm * 8];
            *(float4*)&a8[4] = *(const float4*)&As[kk][tm * 8 + 4];
            *(float4*)&b4[0] = *(const float4*)&Bs[kk][tn * 4];
#pragma unroll
            for (int i = 0; i < 8; ++i)
#pragma unroll
                for (int j = 0; j < 4; ++j)
                    acc[i][j] = fmaf(a8[i], b4[j], acc[i][j]);
        }
    }
    float bias4[4] = {0.f, 0.f, 0.f, 0.f};
    if (MODE == 1 || MODE == 2) {
#pragma unroll
        for (int j = 0; j < 4; ++j) bias4[j] = bias[n0b + tn * 4 + j];
    }
#pragma unroll
    for (int i = 0; i < 8; ++i) {
        size_t row = (size_t)(m0b + tm * 8 + i) * ldc + n0b + tn * 4;
        float4 v;
        float vv[4];
#pragma unroll
        for (int j = 0; j < 4; ++j) {
            float t = acc[i][j];
            if (MODE == 1) t += bias4[j];
            if (MODE == 2) t = tanhf(t + bias4[j]);
            vv[j] = t;
        }
        if (MODE == 3) {
            float4 av = *(const float4*)(aux + row);
            vv[0] = av.x / (1.f + __expf(-vv[0]));
            vv[1] = av.y / (1.f + __expf(-vv[1]));
            vv[2] = av.z / (1.f + __expf(-vv[2]));
            vv[3] = av.w / (1.f + __expf(-vv[3]));
        }
        v.x = vv[0]; v.y = vv[1]; v.z = vv[2]; v.w = vv[3];
        *(float4*)(C + row) = v;
    }
}

// ---------------- GRU scan: 16 clusters x 8 CTAs, st.async + tx mbarriers ----
// cluster = one batch. CTA rank r owns j in [r*32, r*32+32). 8 threads per j.
// Step t reads h[t&1], writes h[(t+1)&1] on ALL ranks via st.async which
// deposits 4 bytes of tx into the destination's mbar[t&1]. Each CTA expects
// 256*4 = 1024 bytes per step. No fences, no syncthreads in the loop.
__global__ void __launch_bounds__(256, 1) __cluster_dims__(8, 1, 1)
scan_kernel(const float* __restrict__ xg, const float* __restrict__ Whh,
            const float* __restrict__ bhh, const float* __restrict__ h0)
{
    __shared__ __align__(16) float h[2][256];
    __shared__ __align__(8) unsigned long long mbar[2];
    int tid  = threadIdx.x;
    int rank = blockIdx.x & 7;
    int b    = blockIdx.x >> 3;
    int pair = tid >> 3;          // 0..31
    int sub  = tid & 7;
    int j    = rank * 32 + pair;  // 0..255

    float4 w[3][8];
#pragma unroll
    for (int g = 0; g < 3; ++g) {
        const float* row = Whh + (size_t)(g * 256 + j) * 256;
#pragma unroll
        for (int i = 0; i < 8; ++i)
            w[g][i] = *(const float4*)(row + i * 32 + sub * 4);
    }
    float b_r = 0.f, b_z = 0.f, b_n = 0.f;
    if (sub == 0) { b_r = bhh[j]; b_z = bhh[256 + j]; b_n = bhh[512 + j]; }

    uint32_t barloc[2] = { smem_u32(&mbar[0]), smem_u32(&mbar[1]) };
    if (tid == 0) {
        asm volatile("mbarrier.init.shared.b64 [%0], 1;" :: "r"(barloc[0]) : "memory");
        asm volatile("mbarrier.init.shared.b64 [%0], 1;" :: "r"(barloc[1]) : "memory");
    }
    h[0][tid] = h0[b * 256 + tid];
    uint32_t hbase[2] = { smem_u32(&h[0][0]), smem_u32(&h[1][0]) };

    // owner lanes: remote data addresses + remote mbar addresses for all ranks
    uint32_t raddr[2][8];   // [dest buffer][rank] -> remote &h[buf][j]
    uint32_t rmbar[2][8];   // [mbar idx][rank]    -> remote &mbar[idx]
    if (sub == 0) {
#pragma unroll
        for (int rk = 0; rk < 8; ++rk) {
            raddr[0][rk] = mapa_rank(hbase[0] + (uint32_t)j * 4u, rk);
            raddr[1][rk] = mapa_rank(hbase[1] + (uint32_t)j * 4u, rk);
            rmbar[0][rk] = mapa_rank(barloc[0], rk);
            rmbar[1][rk] = mapa_rank(barloc[1], rk);
        }
    }
    __syncthreads();
    asm volatile("barrier.cluster.arrive.aligned;" ::: "memory");
    asm volatile("barrier.cluster.wait.aligned;"  ::: "memory");

    // xg prefetch for t=0
    float xr = 0.f, xz = 0.f, xn = 0.f;
    if (sub == 0) {
        const float* xrow = xg + (size_t)(b * 512) * 768;
        xr = xrow[j]; xz = xrow[256 + j]; xn = xrow[512 + j];
    }

    for (int t = 0; t < 512; ++t) {
        int p = t & 1;
        // post this step's tx expectation (1024 bytes) — negative counts are OK
        if (tid == 0) {
            asm volatile("mbarrier.arrive.expect_tx.shared.b64 _, [%0], 1024;"
                         :: "r"(barloc[p]) : "memory");
        }
        float hold = 0.f;
        if (sub == 0) hold = h[p][j];
        float ar = 0.f, az = 0.f, an = 0.f;
#pragma unroll
        for (int i = 0; i < 8; ++i) {
            float4 hv = *(const float4*)&h[p][i * 32 + sub * 4];
            ar = fmaf(w[0][i].x, hv.x, ar); ar = fmaf(w[0][i].y, hv.y, ar);
            ar = fmaf(w[0][i].z, hv.z, ar); ar = fmaf(w[0][i].w, hv.w, ar);
            az = fmaf(w[1][i].x, hv.x, az); az = fmaf(w[1][i].y, hv.y, az);
            az = fmaf(w[1][i].z, hv.z, az); az = fmaf(w[1][i].w, hv.w, az);
            an = fmaf(w[2][i].x, hv.x, an); an = fmaf(w[2][i].y, hv.y, an);
            an = fmaf(w[2][i].z, hv.z, an); an = fmaf(w[2][i].w, hv.w, an);
        }
#pragma unroll
        for (int off = 4; off; off >>= 1) {
            ar += __shfl_down_sync(0xffffffffu, ar, off, 8);
            az += __shfl_down_sync(0xffffffffu, az, off, 8);
            an += __shfl_down_sync(0xffffffffu, an, off, 8);
        }
        if (sub == 0) {
            float r_ = 1.f / (1.f + __expf(-(xr + ar + b_r)));
            float z_ = 1.f / (1.f + __expf(-(xz + az + b_z)));
            float n_ = tanhf(xn + r_ * (an + b_n));
            float hv = (1.f - z_) * n_ + z_ * hold;
            g_out[(size_t)(b * 512 + t) * 256 + j] = hv;
            // broadcast h to all 8 CTAs; each store deposits 4B tx into mbar[p]
#pragma unroll
            for (int rk = 0; rk < 8; ++rk)
                st_async_f32(raddr[p ^ 1][rk], hv, rmbar[p][rk]);
        }
        // prefetch next xg while stores are in flight
        if (sub == 0 && t < 511) {
            const float* xrow = xg + (size_t)(b * 512 + t + 1) * 768;
            xr = xrow[j]; xz = xrow[256 + j]; xn = xrow[512 + j];
        }
        // wait: all 256 h values for step t+1 arrived locally
        {
            uint32_t parity = (uint32_t)((t >> 1) & 1);
            asm volatile(
                "{\n\t"
                ".reg .pred P1;\n\t"
                "WL_%=:\n\t"
                "mbarrier.try_wait.parity.acquire.cta.shared::cta.b64 P1, [%0], %1, 0x989680;\n\t"
                "@P1 bra.uni WD_%=;\n\t"
                "bra.uni WL_%=;\n\t"
                "WD_%=:\n\t"
                "}"
                :: "r"(barloc[p]), "r"(parity) : "memory");
        }
    }
}

// ---------------- attention logits: a = u @ W2^T + b2 ------------------------
__global__ void __launch_bounds__(256) logits_kernel(const float* __restrict__ W2,
                                                     const float* __restrict__ b2) {
    __shared__ float sW[8 * 256];
    for (int i = threadIdx.x; i < 2048; i += 256) sW[i] = W2[i];
    __syncthreads();
    int warp = threadIdx.x >> 5, lane = threadIdx.x & 31;
    int m = blockIdx.x * 8 + warp;
    const float* ur = g_u + (size_t)m * 256;
    float uv[8];
#pragma unroll
    for (int i = 0; i < 8; ++i) uv[i] = ur[i * 32 + lane];
#pragma unroll
    for (int hh = 0; hh < 8; ++hh) {
        float acc = 0.f;
#pragma unroll
        for (int i = 0; i < 8; ++i) acc = fmaf(uv[i], sW[hh * 256 + i * 32 + lane], acc);
#pragma unroll
        for (int off = 16; off; off >>= 1) acc += __shfl_down_sync(0xffffffffu, acc, off);
        if (lane == 0) g_a[(size_t)m * 8 + hh] = acc + b2[hh];
    }
}

// ---------------- masked softmax over T --------------------------------------
__global__ void softmax_kernel(const int* __restrict__ lengths, float* __restrict__ att) {
    int bh = blockIdx.x, b = bh >> 3, hh = bh & 7;
    int t = threadIdx.x;
    int len = lengths[b];
    float v = (t < len) ? g_a[(size_t)(b * 512 + t) * 8 + hh] : -1e30f;
    __shared__ float red[16];
    __shared__ float bc[2];
    float m = v;
#pragma unroll
    for (int o = 16; o; o >>= 1) m = fmaxf(m, __shfl_xor_sync(0xffffffffu, m, o));
    if ((t & 31) == 0) red[t >> 5] = m;
    __syncthreads();
    if (t == 0) {
        float mm = red[0];
        for (int i = 1; i < 16; ++i) mm = fmaxf(mm, red[i]);
        bc[0] = mm;
    }
    __syncthreads();
    float e = __expf(v - bc[0]);
    float s = e;
#pragma unroll
    for (int o = 16; o; o >>= 1) s += __shfl_xor_sync(0xffffffffu, s, o);
    __syncthreads();
    if ((t & 31) == 0) red[t >> 5] = s;
    __syncthreads();
    if (t == 0) {
        float ss = 0.f;
        for (int i = 0; i < 16; ++i) ss += red[i];
        bc[1] = ss;
    }
    __syncthreads();
    att[(size_t)bh * 512 + t] = e / bc[1];
}

// ---------------- sent + avg (+hn copy) --------------------------------------
__global__ void __launch_bounds__(256) sent_kernel(const float* __restrict__ att,
                                                   float* __restrict__ out_hn) {
    int b = blockIdx.x, q = blockIdx.y;
    __shared__ float sat[8][512];
    __shared__ float sred[4][8][64];
    int tid = threadIdx.x;
    for (int i = tid; i < 4096; i += 256) sat[i >> 9][i & 511] = att[(size_t)b * 4096 + i];
    __syncthreads();
    int dl = tid & 63, tc = tid >> 6;
    int d = q * 64 + dl;
    const float* orow = g_out + (size_t)b * 512 * 256;
    float acc[8] = {0.f,0.f,0.f,0.f,0.f,0.f,0.f,0.f};
    for (int t = tc * 128; t < tc * 128 + 128; ++t) {
        float ov = orow[(size_t)t * 256 + d];
#pragma unroll
        for (int hh = 0; hh < 8; ++hh) acc[hh] = fmaf(sat[hh][t], ov, acc[hh]);
    }
#pragma unroll
    for (int hh = 0; hh < 8; ++hh) sred[tc][hh][dl] = acc[hh];
    __syncthreads();
    if (tc == 0) {
        float s = 0.f;
#pragma unroll
        for (int hh = 0; hh < 8; ++hh)
            s += sred[0][hh][dl] + sred[1][hh][dl] + sred[2][hh][dl] + sred[3][hh][dl];
        g_sent[b * 256 + d] = s * 0.125f;
        out_hn[b * 256 + d] = orow[(size_t)511 * 256 + d];
    }
}

// ---------------- final FC ---------------------------------------------------
__global__ void fc_kernel(const float* __restrict__ Wf, const float* __restrict__ bf,
                          float* __restrict__ out_main) {
    int b = blockIdx.x;
    __shared__ float sv[256];
    sv[threadIdx.x] = g_sent[b * 256 + threadIdx.x];
    __syncthreads();
    if (threadIdx.x < 10) {
        float s = bf[threadIdx.x];
        for (int k = 0; k < 256; ++k) s = fmaf(Wf[threadIdx.x * 256 + k], sv[k], s);
        out_main[b * 10 + threadIdx.x] = s;
    }
}

// ============================================================================
extern "C" void kernel_launch(void* const* d_in, const int* in_sizes, int n_in,
                              void* d_out, int out_size) {
    const int*   x    = (const int*)  d_in[0];
    const int*   len  = (const int*)  d_in[1];
    const float* h0   = (const float*)d_in[2];
    const float* emb  = (const float*)d_in[3];
    const float* G    = (const float*)d_in[4];
    const float* Gp   = (const float*)d_in[5];
    const float* mw   = (const float*)d_in[6];
    const float* Wc1  = (const float*)d_in[7];
    const float* Wc2  = (const float*)d_in[8];
    const float* W_ih = (const float*)d_in[9];
    const float* W_hh = (const float*)d_in[10];
    const float* b_ih = (const float*)d_in[11];
    const float* b_hh = (const float*)d_in[12];
    const float* W1   = (const float*)d_in[13];
    const float* b1   = (const float*)d_in[14];
    const float* W2   = (const float*)d_in[15];
    const float* b2   = (const float*)d_in[16];
    const float* Wf   = (const float*)d_in[17];
    const float* bf   = (const float*)d_in[18];

    float* out      = (float*)d_out;
    float* out_main = out;
    float* out_hn   = out + 160;
    float* out_att  = out + 160 + 4096;

    void* p;
    cudaGetSymbolAddress(&p, g_M);    float* pM    = (float*)p;
    cudaGetSymbolAddress(&p, g_cat);  float* pcat  = (float*)p;
    cudaGetSymbolAddress(&p, g_c1);   float* pc1   = (float*)p;
    cudaGetSymbolAddress(&p, g_next); float* pnext = (float*)p;
    cudaGetSymbolAddress(&p, g_xg);   float* pxg   = (float*)p;
    cudaGetSymbolAddress(&p, g_out);  float* pout  = (float*)p;
    cudaGetSymbolAddress(&p, g_u);    float* pu    = (float*)p;

    // 1. embedding gather
    embed_kernel<<<8192, 64>>>(x, emb);
    // 2. adjacency mix
    mix_kernel<<<4096, 256>>>(G, Gp, mw);
    // 3. weighted = M^T @ Hemb -> cat right half
    gemm128<1, 0, 0><<<dim3(4, 4, 16), 256>>>(
        pM, 512, pcat, 512, pcat + 256, 512, 512, nullptr, nullptr,
        (size_t)512 * 512, (size_t)512 * 512, (size_t)512 * 512);
    // 4. c1 = cat @ Wc1^T
    gemm128<0, 1, 0><<<dim3(64, 4), 256>>>(
        pcat, 512, Wc1, 512, pc1, 256, 512, nullptr, nullptr, 0, 0, 0);
    // 5. next = c1 * sigmoid(cat @ Wc2^T)
    gemm128<0, 1, 3><<<dim3(64, 4), 256>>>(
        pcat, 512, Wc2, 512, pnext, 256, 512, nullptr, pc1, 0, 0, 0);
    // 6. xg = next @ W_ih^T + b_ih
    gemm128<0, 1, 1><<<dim3(64, 12), 256>>>(
        pnext, 256, W_ih, 256, pxg, 768, 256, b_ih, nullptr, 0, 0, 0);
    // 7. GRU scan (st.async + tx mbarriers)
    scan_kernel<<<128, 256>>>(pxg, W_hh, b_hh, h0);
    // 8. u = tanh(out @ W1^T + b1)
    gemm128<0, 1, 2><<<dim3(64, 4), 256>>>(
        pout, 256, W1, 256, pu, 256, 256, b1, nullptr, 0, 0, 0);
    // 9. logits
    logits_kernel<<<1024, 256>>>(W2, b2);
    // 10. masked softmax
    softmax_kernel<<<128, 512>>>(len, out_att);
    // 11. sent + avg + hn
    sent_kernel<<<dim3(16, 4), 256>>>(out_att, out_hn);
    // 12. final FC
    fc_kernel<<<16, 256>>>(Wf, bf, out_main);
}